// round 9
// baseline (speedup 1.0000x reference)
#include <cuda_runtime.h>
#include <cuda_fp16.h>
#include <math_constants.h>

#define NB 128
#define N 1024
#define NITERS 20
#define GROUP 16
#define NGROUPS (NB / GROUP)
#define LOG2E 1.44269504088896340736f

// s in LOG2 domain (fp32, iteration 1 only). s_shift = s - R1 - C1 stored in
// fp16 BOTH row-major (g_h) and transposed (g_hT). Shifted-domain updates are
// absolute: Rr = log2 sum_j 2^(s-Cr_j), Cr = log2 sum_i 2^(s-Rr_i) — so both
// half-iterations are the SAME dense row-streaming kernel.
static __device__ float  g_s[(size_t)NB * N * N];        // 512 MB
static __device__ __half g_h[(size_t)NB * N * N];        // 256 MB
static __device__ __half g_hT[(size_t)GROUP * N * N];    // 32 MB (per group)
static __device__ float g_R[NB * N], g_C[NB * N];        // absolute (iter 1)
static __device__ float g_Rr[NB * N], g_Cr[NB * N];      // shifted-domain

__device__ __forceinline__ float ex2(float x) {
    float y;
    asm("ex2.approx.ftz.f32 %0, %1;" : "=f"(y) : "f"(x));
    return y;
}

// ---------------------------------------------------------------------------
// FUSED init + iter-1 row pass. Warp per row: Gumbel transform in registers
// (accurate logf inner), write s once, exact-max row LSE -> R1.
// ---------------------------------------------------------------------------
__global__ void __launch_bounds__(256) gs_init_row(const float* __restrict__ la,
                                                   const float* __restrict__ noise,
                                                   int b0) {
    const float EPS = 1e-20f;
    const float SC = 10.0f * LOG2E;
    int lane = threadIdx.x & 31, w = threadIdx.x >> 5;
    int rglob = b0 * N + blockIdx.x * 8 + w;
    const float4* __restrict__ arow =
        reinterpret_cast<const float4*>(la + (size_t)rglob * N);
    const float4* __restrict__ urow =
        reinterpret_cast<const float4*>(noise + (size_t)rglob * N);
    float4* __restrict__ srow = reinterpret_cast<float4*>(g_s + (size_t)rglob * N);

    float4 sv[8];
#pragma unroll
    for (int k = 0; k < 8; k++) {
        float4 a = arow[k * 32 + lane];
        float4 u = urow[k * 32 + lane];
        sv[k].x = (a.x - __logf(EPS - logf(u.x + EPS))) * SC;
        sv[k].y = (a.y - __logf(EPS - logf(u.y + EPS))) * SC;
        sv[k].z = (a.z - __logf(EPS - logf(u.z + EPS))) * SC;
        sv[k].w = (a.w - __logf(EPS - logf(u.w + EPS))) * SC;
        srow[k * 32 + lane] = sv[k];
    }
    float m = -CUDART_INF_F;
#pragma unroll
    for (int k = 0; k < 8; k++)
        m = fmaxf(m, fmaxf(fmaxf(sv[k].x, sv[k].y), fmaxf(sv[k].z, sv[k].w)));
#pragma unroll
    for (int o = 16; o; o >>= 1) m = fmaxf(m, __shfl_xor_sync(~0u, m, o));
    float a0 = 0.f, a1 = 0.f;
#pragma unroll
    for (int k = 0; k < 8; k++) {
        a0 += ex2(sv[k].x - m) + ex2(sv[k].y - m);
        a1 += ex2(sv[k].z - m) + ex2(sv[k].w - m);
    }
    float sum = a0 + a1;
#pragma unroll
    for (int o = 16; o; o >>= 1) sum += __shfl_xor_sync(~0u, sum, o);
    if (lane == 0) g_R[rglob] = m + __log2f(sum);
}

// ---------------------------------------------------------------------------
// Iter-1 col pass (fp32, strided — runs once): C1 = log2 sum_i 2^(s - R1_i).
// ---------------------------------------------------------------------------
__global__ void __launch_bounds__(512) gs_col_first(int b0) {
    __shared__ float sr[N];
    __shared__ float part[16][33];
    int tid = threadIdx.x, lane = tid & 31, w = tid >> 5;
    int b = b0 + blockIdx.y;
    int j = blockIdx.x * 32 + lane;
    if (tid < 256)
        reinterpret_cast<float4*>(sr)[tid] =
            reinterpret_cast<const float4*>(g_R + (size_t)b * N)[tid];
    __syncthreads();
    const float* __restrict__ sp = g_s + (size_t)b * N * N + j;
    int i0 = w * 64;
    float acc0 = 0.f, acc1 = 0.f;
#pragma unroll
    for (int ii = 0; ii < 64; ii += 8) {
        float v[8];
#pragma unroll
        for (int q = 0; q < 8; q++) v[q] = sp[(size_t)(i0 + ii + q) * N];
#pragma unroll
        for (int q = 0; q < 8; q += 2) {
            acc0 += ex2(v[q]     - sr[i0 + ii + q]);
            acc1 += ex2(v[q + 1] - sr[i0 + ii + q + 1]);
        }
    }
    part[w][lane] = acc0 + acc1;
    __syncthreads();
    if (w == 0) {
        float t = 0.f;
#pragma unroll
        for (int k = 0; k < 16; k++) t += part[k][lane];
        g_C[(size_t)b * N + j] = __log2f(t);
    }
}

// ---------------------------------------------------------------------------
// Iter-2 row pass FUSED with fp16 pack. __ldcs on s (last use, evict-first).
// s_shift = s - R1 - C1 (<= 0) as half; Rr = log2(rowsum).
// ---------------------------------------------------------------------------
__global__ void __launch_bounds__(256) gs_row_pack(int b0) {
    __shared__ float sc[N];
    int tid = threadIdx.x, lane = tid & 31, w = tid >> 5;
    int b = b0 + (blockIdx.x >> 7);
    int row = ((blockIdx.x & 127) << 3) + w;
    reinterpret_cast<float4*>(sc)[tid] =
        reinterpret_cast<const float4*>(g_C + (size_t)b * N)[tid];
    __syncthreads();

    const float4* __restrict__ srow =
        reinterpret_cast<const float4*>(g_s + ((size_t)b * N + row) * N);
    uint2* hrow = reinterpret_cast<uint2*>(g_h + ((size_t)b * N + row) * N);
    const float4* scv = reinterpret_cast<const float4*>(sc);
    float r1 = g_R[(size_t)b * N + row];

    float a0 = 0.f, a1 = 0.f;
#pragma unroll
    for (int h = 0; h < 2; h++) {
        float4 sv[4];
#pragma unroll
        for (int k = 0; k < 4; k++) sv[k] = __ldcs(&srow[h * 128 + k * 32 + lane]);
#pragma unroll
        for (int k = 0; k < 4; k++) {
            int idx = h * 128 + k * 32 + lane;
            float4 cv = scv[idx];
            float ax = sv[k].x - cv.x - r1, ay = sv[k].y - cv.y - r1;
            float az = sv[k].z - cv.z - r1, aw = sv[k].w - cv.w - r1;
            a0 += ex2(ax) + ex2(ay);
            a1 += ex2(az) + ex2(aw);
            __half2 h01 = __floats2half2_rn(ax, ay);
            __half2 h23 = __floats2half2_rn(az, aw);
            uint2 pv;
            pv.x = *reinterpret_cast<unsigned*>(&h01);
            pv.y = *reinterpret_cast<unsigned*>(&h23);
            hrow[idx] = pv;
        }
    }
    float sum = a0 + a1;
#pragma unroll
    for (int o = 16; o; o >>= 1) sum += __shfl_xor_sync(~0u, sum, o);
    if (lane == 0) g_Rr[(size_t)b * N + row] = __log2f(sum);
}

// ---------------------------------------------------------------------------
// 64x64 SMEM transpose: g_h (group slice) -> g_hT. Runs once per group.
// Padding 66 makes the column gather conflict-light.
// ---------------------------------------------------------------------------
__global__ void __launch_bounds__(256) gs_transpose(int b0) {
    __shared__ __half tile[64][66];
    int t = threadIdx.x;
    int bl = blockIdx.z;
    const __half* __restrict__ src =
        g_h + ((size_t)(b0 + bl) * N + blockIdx.y * 64) * N + blockIdx.x * 64;
    __half* __restrict__ dst =
        g_hT + ((size_t)bl * N + blockIdx.x * 64) * N + blockIdx.y * 64;
#pragma unroll
    for (int hh = 0; hh < 2; hh++) {
        int idx = t + hh * 256;
        int row = idx >> 3, c4 = idx & 7;
        __half tmp[8];
        *reinterpret_cast<uint4*>(tmp) =
            *reinterpret_cast<const uint4*>(src + (size_t)row * N + c4 * 8);
#pragma unroll
        for (int k = 0; k < 8; k++) tile[row][c4 * 8 + k] = tmp[k];
    }
    __syncthreads();
#pragma unroll
    for (int hh = 0; hh < 2; hh++) {
        int idx = t + hh * 256;
        int trow = idx >> 3, c4 = idx & 7;
        __half tmp[8];
#pragma unroll
        for (int k = 0; k < 8; k++) tmp[k] = tile[c4 * 8 + k][trow];
        *reinterpret_cast<uint4*>(dst + (size_t)trow * N + c4 * 8) =
            *reinterpret_cast<uint4*>(tmp);
    }
}

// ---------------------------------------------------------------------------
// Unified fp16 pass (both half-iterations): warp-per-row dense stream.
//   mode 0 (row): mat = h,  vin = Cr (SMEM), vout = Rr
//   mode 1 (col): mat = hT, vin = Rr (SMEM), vout = Cr
// vout = log2 sum ex2(mat_row[j] - vin[j])   (absolute update).
// ---------------------------------------------------------------------------
__global__ void __launch_bounds__(256) gs_pass(int b0, int mode) {
    __shared__ float sv[N];
    int tid = threadIdx.x, lane = tid & 31, w = tid >> 5;
    int bl = blockIdx.x >> 7;
    int row = ((blockIdx.x & 127) << 3) + w;

    const __half* mat;
    const float* vin;
    float* vout;
    if (mode == 0) {
        mat  = g_h + ((size_t)(b0 + bl) * N + row) * N;
        vin  = g_Cr + (size_t)(b0 + bl) * N;
        vout = g_Rr + (size_t)(b0 + bl) * N + row;
    } else {
        mat  = g_hT + ((size_t)bl * N + row) * N;
        vin  = g_Rr + (size_t)(b0 + bl) * N;
        vout = g_Cr + (size_t)(b0 + bl) * N + row;
    }
    reinterpret_cast<float4*>(sv)[tid] =
        reinterpret_cast<const float4*>(vin)[tid];
    __syncthreads();

    const uint4* __restrict__ hrow = reinterpret_cast<const uint4*>(mat);
    uint4 hv[4];
#pragma unroll
    for (int k = 0; k < 4; k++) hv[k] = hrow[k * 32 + lane];

    const float4* svv = reinterpret_cast<const float4*>(sv);
    float a0 = 0.f, a1 = 0.f;
#pragma unroll
    for (int k = 0; k < 4; k++) {
        int i = k * 32 + lane;
        float4 c0 = svv[2 * i], c1 = svv[2 * i + 1];
        float2 f0 = __half22float2(*reinterpret_cast<__half2*>(&hv[k].x));
        float2 f1 = __half22float2(*reinterpret_cast<__half2*>(&hv[k].y));
        float2 f2 = __half22float2(*reinterpret_cast<__half2*>(&hv[k].z));
        float2 f3 = __half22float2(*reinterpret_cast<__half2*>(&hv[k].w));
        a0 += ex2(f0.x - c0.x) + ex2(f0.y - c0.y);
        a1 += ex2(f1.x - c0.z) + ex2(f1.y - c0.w);
        a0 += ex2(f2.x - c1.x) + ex2(f2.y - c1.y);
        a1 += ex2(f3.x - c1.z) + ex2(f3.y - c1.w);
    }
    float sum = a0 + a1;
#pragma unroll
    for (int o = 16; o; o >>= 1) sum += __shfl_xor_sync(~0u, sum, o);
    if (lane == 0) *vout = __log2f(sum);
}

// ---------------------------------------------------------------------------
// Final: out = exp2(s_shift - Rr - Cr).
// ---------------------------------------------------------------------------
__global__ void __launch_bounds__(256) gs_final(float* __restrict__ out, int b0) {
    size_t t8 = (size_t)blockIdx.x * 256 + threadIdx.x;
    size_t e = (size_t)b0 * N * N + t8 * 8;
    int row = (int)(e >> 10);
    int b = row >> 10;
    int j = (int)(e & (N - 1));
    float r = g_Rr[row];
    float4 c0 = *reinterpret_cast<const float4*>(g_Cr + (size_t)b * N + j);
    float4 c1 = *reinterpret_cast<const float4*>(g_Cr + (size_t)b * N + j + 4);
    uint4 hv = __ldcs(reinterpret_cast<const uint4*>(g_h + e));
    float2 f0 = __half22float2(*reinterpret_cast<__half2*>(&hv.x));
    float2 f1 = __half22float2(*reinterpret_cast<__half2*>(&hv.y));
    float2 f2 = __half22float2(*reinterpret_cast<__half2*>(&hv.z));
    float2 f3 = __half22float2(*reinterpret_cast<__half2*>(&hv.w));
    float4 o0, o1;
    o0.x = ex2(f0.x - r - c0.x); o0.y = ex2(f0.y - r - c0.y);
    o0.z = ex2(f1.x - r - c0.z); o0.w = ex2(f1.y - r - c0.w);
    o1.x = ex2(f2.x - r - c1.x); o1.y = ex2(f2.y - r - c1.y);
    o1.z = ex2(f3.x - r - c1.z); o1.w = ex2(f3.y - r - c1.w);
    *reinterpret_cast<float4*>(out + e) = o0;
    *reinterpret_cast<float4*>(out + e + 4) = o1;
}

// ---------------------------------------------------------------------------
// 8 groups of 16 batches; h + hT (64 MB) stay L2-resident per group.
// ---------------------------------------------------------------------------
extern "C" void kernel_launch(void* const* d_in, const int* in_sizes, int n_in,
                              void* d_out, int out_size) {
    const float* la = (const float*)d_in[0];
    const float* noise = (const float*)d_in[1];
    float* out = (float*)d_out;

    for (int g = 0; g < NGROUPS; g++) {
        int b0 = g * GROUP;
        gs_init_row<<<(GROUP * N) / 8, 256>>>(la, noise, b0);   // init + iter-1 row
        gs_col_first<<<dim3(N / 32, GROUP), 512>>>(b0);         // iter-1 col
        gs_row_pack<<<(GROUP * N) / 8, 256>>>(b0);              // iter-2 row + pack h
        gs_transpose<<<dim3(16, 16, GROUP), 256>>>(b0);         // h -> hT
        gs_pass<<<(GROUP * N) / 8, 256>>>(b0, 1);               // iter-2 col
        for (int t = 3; t <= NITERS; t++) {
            gs_pass<<<(GROUP * N) / 8, 256>>>(b0, 0);           // row
            gs_pass<<<(GROUP * N) / 8, 256>>>(b0, 1);           // col
        }
        gs_final<<<(GROUP * N * N) / (256 * 8), 256>>>(out, b0);
    }
}

// round 10
// speedup vs baseline: 1.3654x; 1.3654x over previous
#include <cuda_runtime.h>
#include <cuda_fp16.h>
#include <math_constants.h>

#define NB 128
#define N 1024
#define NITERS 20
#define GROUP 32
#define NGROUPS (NB / GROUP)
#define LOG2E 1.44269504088896340736f

// s in LOG2 domain (fp32, iteration 1 only); s_shift = s - R1 - C1 (fp16)
// for iterations 2..20 + final. Shifted-domain updates are ABSOLUTE:
// Rr = log2 sum_j 2^(s-Cr_j), Cr = log2 sum_i 2^(s-Rr_i).
static __device__ float  g_s[(size_t)NB * N * N];    // 512 MB
static __device__ __half g_h[(size_t)NB * N * N];    // 256 MB
static __device__ float g_R[NB * N], g_C[NB * N];    // absolute (iter 1)
static __device__ float g_Rr[NB * N], g_Cr[NB * N];  // shifted-domain

__device__ __forceinline__ float ex2(float x) {
    float y;
    asm("ex2.approx.ftz.f32 %0, %1;" : "=f"(y) : "f"(x));
    return y;
}

// ---------------------------------------------------------------------------
// FUSED init + iter-1 row pass. Warp per row: Gumbel transform in registers
// (accurate logf inner — extremes dominate the row max), write s once,
// exact-max row LSE -> R1.
// ---------------------------------------------------------------------------
__global__ void __launch_bounds__(256) gs_init_row(const float* __restrict__ la,
                                                   const float* __restrict__ noise,
                                                   int b0) {
    const float EPS = 1e-20f;
    const float SC = 10.0f * LOG2E;
    int lane = threadIdx.x & 31, w = threadIdx.x >> 5;
    int rglob = b0 * N + blockIdx.x * 8 + w;
    const float4* __restrict__ arow =
        reinterpret_cast<const float4*>(la + (size_t)rglob * N);
    const float4* __restrict__ urow =
        reinterpret_cast<const float4*>(noise + (size_t)rglob * N);
    float4* __restrict__ srow = reinterpret_cast<float4*>(g_s + (size_t)rglob * N);

    float4 sv[8];
#pragma unroll
    for (int k = 0; k < 8; k++) {
        float4 a = arow[k * 32 + lane];
        float4 u = urow[k * 32 + lane];
        sv[k].x = (a.x - __logf(EPS - logf(u.x + EPS))) * SC;
        sv[k].y = (a.y - __logf(EPS - logf(u.y + EPS))) * SC;
        sv[k].z = (a.z - __logf(EPS - logf(u.z + EPS))) * SC;
        sv[k].w = (a.w - __logf(EPS - logf(u.w + EPS))) * SC;
        srow[k * 32 + lane] = sv[k];
    }
    float m = -CUDART_INF_F;
#pragma unroll
    for (int k = 0; k < 8; k++)
        m = fmaxf(m, fmaxf(fmaxf(sv[k].x, sv[k].y), fmaxf(sv[k].z, sv[k].w)));
#pragma unroll
    for (int o = 16; o; o >>= 1) m = fmaxf(m, __shfl_xor_sync(~0u, m, o));
    float a0 = 0.f, a1 = 0.f;
#pragma unroll
    for (int k = 0; k < 8; k++) {
        a0 += ex2(sv[k].x - m) + ex2(sv[k].y - m);
        a1 += ex2(sv[k].z - m) + ex2(sv[k].w - m);
    }
    float sum = a0 + a1;
#pragma unroll
    for (int o = 16; o; o >>= 1) sum += __shfl_xor_sync(~0u, sum, o);
    if (lane == 0) g_R[rglob] = m + __log2f(sum);
}

// ---------------------------------------------------------------------------
// Iter-1 col pass (fp32): C1 = log2 sum_i 2^(s - R1_i); args <= 0 (LSE bound).
// ---------------------------------------------------------------------------
__global__ void __launch_bounds__(512) gs_col_first(int b0) {
    __shared__ float sr[N];
    __shared__ float part[16][33];
    int tid = threadIdx.x, lane = tid & 31, w = tid >> 5;
    int b = b0 + blockIdx.y;
    int j = blockIdx.x * 32 + lane;
    if (tid < 256)
        reinterpret_cast<float4*>(sr)[tid] =
            reinterpret_cast<const float4*>(g_R + (size_t)b * N)[tid];
    __syncthreads();
    const float* __restrict__ sp = g_s + (size_t)b * N * N + j;
    int i0 = w * 64;
    float acc0 = 0.f, acc1 = 0.f;
#pragma unroll
    for (int ii = 0; ii < 64; ii += 8) {
        float v[8];
#pragma unroll
        for (int q = 0; q < 8; q++) v[q] = sp[(size_t)(i0 + ii + q) * N];
#pragma unroll
        for (int q = 0; q < 8; q += 2) {
            acc0 += ex2(v[q]     - sr[i0 + ii + q]);
            acc1 += ex2(v[q + 1] - sr[i0 + ii + q + 1]);
        }
    }
    part[w][lane] = acc0 + acc1;
    __syncthreads();
    if (w == 0) {
        float t = 0.f;
#pragma unroll
        for (int k = 0; k < 16; k++) t += part[k][lane];
        g_C[(size_t)b * N + j] = __log2f(t);
    }
}

// ---------------------------------------------------------------------------
// Iter-2 row pass FUSED with fp16 pack. __ldcs on s (last use, evict-first).
// s_shift = s - R1 - C1 (<= 0) as half; Rr = log2(rowsum).
// ---------------------------------------------------------------------------
__global__ void __launch_bounds__(256) gs_row_pack(int b0) {
    __shared__ float sc[N];
    int tid = threadIdx.x, lane = tid & 31, w = tid >> 5;
    int b = b0 + (blockIdx.x >> 7);
    int row = ((blockIdx.x & 127) << 3) + w;
    reinterpret_cast<float4*>(sc)[tid] =
        reinterpret_cast<const float4*>(g_C + (size_t)b * N)[tid];
    __syncthreads();

    const float4* __restrict__ srow =
        reinterpret_cast<const float4*>(g_s + ((size_t)b * N + row) * N);
    uint2* hrow = reinterpret_cast<uint2*>(g_h + ((size_t)b * N + row) * N);
    const float4* scv = reinterpret_cast<const float4*>(sc);
    float r1 = g_R[(size_t)b * N + row];

    float a0 = 0.f, a1 = 0.f;
#pragma unroll
    for (int h = 0; h < 2; h++) {
        float4 sv[4];
#pragma unroll
        for (int k = 0; k < 4; k++) sv[k] = __ldcs(&srow[h * 128 + k * 32 + lane]);
#pragma unroll
        for (int k = 0; k < 4; k++) {
            int idx = h * 128 + k * 32 + lane;
            float4 cv = scv[idx];
            float ax = sv[k].x - cv.x - r1, ay = sv[k].y - cv.y - r1;
            float az = sv[k].z - cv.z - r1, aw = sv[k].w - cv.w - r1;
            a0 += ex2(ax) + ex2(ay);
            a1 += ex2(az) + ex2(aw);
            __half2 h01 = __floats2half2_rn(ax, ay);
            __half2 h23 = __floats2half2_rn(az, aw);
            uint2 pv;
            pv.x = *reinterpret_cast<unsigned*>(&h01);
            pv.y = *reinterpret_cast<unsigned*>(&h23);
            hrow[idx] = pv;
        }
    }
    float sum = a0 + a1;
#pragma unroll
    for (int o = 16; o; o >>= 1) sum += __shfl_xor_sync(~0u, sum, o);
    if (lane == 0) g_Rr[(size_t)b * N + row] = __log2f(sum);
}

// ---------------------------------------------------------------------------
// fp16 row pass: Rr = log2 sum_j 2^(s_shift - Cr_j)  (absolute update).
// ---------------------------------------------------------------------------
__global__ void __launch_bounds__(256) gs_row_h(int b0) {
    __shared__ float sc[N];
    int tid = threadIdx.x, lane = tid & 31, w = tid >> 5;
    int b = b0 + (blockIdx.x >> 7);
    int row = ((blockIdx.x & 127) << 3) + w;
    reinterpret_cast<float4*>(sc)[tid] =
        reinterpret_cast<const float4*>(g_Cr + (size_t)b * N)[tid];
    __syncthreads();

    const uint4* __restrict__ hrow =
        reinterpret_cast<const uint4*>(g_h + ((size_t)b * N + row) * N);
    uint4 hv[4];
#pragma unroll
    for (int k = 0; k < 4; k++) hv[k] = hrow[k * 32 + lane];

    const float4* scv = reinterpret_cast<const float4*>(sc);
    float a0 = 0.f, a1 = 0.f;
#pragma unroll
    for (int k = 0; k < 4; k++) {
        int i = k * 32 + lane;
        float4 c0 = scv[2 * i], c1 = scv[2 * i + 1];
        float2 f0 = __half22float2(*reinterpret_cast<__half2*>(&hv[k].x));
        float2 f1 = __half22float2(*reinterpret_cast<__half2*>(&hv[k].y));
        float2 f2 = __half22float2(*reinterpret_cast<__half2*>(&hv[k].z));
        float2 f3 = __half22float2(*reinterpret_cast<__half2*>(&hv[k].w));
        a0 += ex2(f0.x - c0.x) + ex2(f0.y - c0.y);
        a1 += ex2(f1.x - c0.z) + ex2(f1.y - c0.w);
        a0 += ex2(f2.x - c1.x) + ex2(f2.y - c1.y);
        a1 += ex2(f3.x - c1.z) + ex2(f3.y - c1.w);
    }
    float sum = a0 + a1;
#pragma unroll
    for (int o = 16; o; o >>= 1) sum += __shfl_xor_sync(~0u, sum, o);
    if (lane == 0) g_Rr[(size_t)b * N + row] = __log2f(sum);
}

// ---------------------------------------------------------------------------
// fp16 col pass: Cr = log2 sum_i 2^(s_shift - Rr_i)  (absolute update).
// Grid (16 jc, GROUP b) = 512 blocks x 512 thr -> ~86% occupancy.
// ---------------------------------------------------------------------------
__global__ void __launch_bounds__(512) gs_col_h(int b0) {
    __shared__ float sr[N];
    __shared__ float part[16][66];
    int tid = threadIdx.x, lane = tid & 31, w = tid >> 5;
    int b = b0 + blockIdx.y;
    int j0 = blockIdx.x * 64;
    if (tid < 256)
        reinterpret_cast<float4*>(sr)[tid] =
            reinterpret_cast<const float4*>(g_Rr + (size_t)b * N)[tid];
    __syncthreads();

    const __half2* __restrict__ hp =
        reinterpret_cast<const __half2*>(g_h + (size_t)b * N * N + j0) + lane;
    int i0 = w * 64;
    float ax = 0.f, ay = 0.f;
#pragma unroll
    for (int ii = 0; ii < 64; ii += 8) {
        __half2 v[8];
#pragma unroll
        for (int q = 0; q < 8; q++) v[q] = hp[(size_t)(i0 + ii + q) * (N / 2)];
#pragma unroll
        for (int q = 0; q < 8; q++) {
            float rr = sr[i0 + ii + q];
            float2 f = __half22float2(v[q]);
            ax += ex2(f.x - rr);
            ay += ex2(f.y - rr);
        }
    }
    part[w][2 * lane] = ax;
    part[w][2 * lane + 1] = ay;
    __syncthreads();
    if (tid < 64) {
        float t = 0.f;
#pragma unroll
        for (int k = 0; k < 16; k++) t += part[k][tid];
        g_Cr[(size_t)b * N + j0 + tid] = __log2f(t);
    }
}

// ---------------------------------------------------------------------------
// Final: out = exp2(s_shift - Rr - Cr).
// ---------------------------------------------------------------------------
__global__ void __launch_bounds__(256) gs_final(float* __restrict__ out, int b0) {
    size_t t8 = (size_t)blockIdx.x * 256 + threadIdx.x;
    size_t e = (size_t)b0 * N * N + t8 * 8;
    int row = (int)(e >> 10);
    int b = row >> 10;
    int j = (int)(e & (N - 1));
    float r = g_Rr[row];
    float4 c0 = *reinterpret_cast<const float4*>(g_Cr + (size_t)b * N + j);
    float4 c1 = *reinterpret_cast<const float4*>(g_Cr + (size_t)b * N + j + 4);
    uint4 hv = __ldcs(reinterpret_cast<const uint4*>(g_h + e));
    float2 f0 = __half22float2(*reinterpret_cast<__half2*>(&hv.x));
    float2 f1 = __half22float2(*reinterpret_cast<__half2*>(&hv.y));
    float2 f2 = __half22float2(*reinterpret_cast<__half2*>(&hv.z));
    float2 f3 = __half22float2(*reinterpret_cast<__half2*>(&hv.w));
    float4 o0, o1;
    o0.x = ex2(f0.x - r - c0.x); o0.y = ex2(f0.y - r - c0.y);
    o0.z = ex2(f1.x - r - c0.z); o0.w = ex2(f1.y - r - c0.w);
    o1.x = ex2(f2.x - r - c1.x); o1.y = ex2(f2.y - r - c1.y);
    o1.z = ex2(f3.x - r - c1.z); o1.w = ex2(f3.y - r - c1.w);
    *reinterpret_cast<float4*>(out + e) = o0;
    *reinterpret_cast<float4*>(out + e + 4) = o1;
}

// ---------------------------------------------------------------------------
// 4 groups of 32 batches; fp16 iteration working set = 64 MB (L2-hot),
// and every iteration kernel now has enough blocks to fill the chip.
// ---------------------------------------------------------------------------
extern "C" void kernel_launch(void* const* d_in, const int* in_sizes, int n_in,
                              void* d_out, int out_size) {
    const float* la = (const float*)d_in[0];
    const float* noise = (const float*)d_in[1];
    float* out = (float*)d_out;

    for (int g = 0; g < NGROUPS; g++) {
        int b0 = g * GROUP;
        gs_init_row<<<(GROUP * N) / 8, 256>>>(la, noise, b0);   // init + iter-1 row
        gs_col_first<<<dim3(N / 32, GROUP), 512>>>(b0);         // iter-1 col
        gs_row_pack<<<(GROUP * N) / 8, 256>>>(b0);              // iter-2 row + pack h
        gs_col_h<<<dim3(N / 64, GROUP), 512>>>(b0);             // iter-2 col
        for (int t = 3; t <= NITERS; t++) {
            gs_row_h<<<(GROUP * N) / 8, 256>>>(b0);
            gs_col_h<<<dim3(N / 64, GROUP), 512>>>(b0);
        }
        gs_final<<<(GROUP * N * N) / (256 * 8), 256>>>(out, b0);
    }
}

// round 12
// speedup vs baseline: 1.4366x; 1.0522x over previous
#include <cuda_runtime.h>
#include <cuda_fp16.h>
#include <math_constants.h>

#define NB 128
#define N 1024
#define NITERS 20
#define GROUP 32
#define NGROUPS (NB / GROUP)
#define LOG2E 1.44269504088896340736f

// h1 = s - R1 in fp16 (log2 domain), R1 exact (fp32 registers, never stored).
// Shifted-domain updates are ABSOLUTE and shift-invariant:
//   Rr^t_i = log2 sum_j 2^(h1 - Cr^{t-1}_j),  Cr^t_j = log2 sum_i 2^(h1 - Rr^t_i)
// with Rr^1 = 0 (R1 baked).  out = 2^(h1 - Rr^20 - Cr^20).
static __device__ __half g_h[(size_t)NB * N * N];    // 256 MB
static __device__ float g_Rr[NB * N], g_Cr[NB * N];

__device__ __forceinline__ float ex2(float x) {
    float y;
    asm("ex2.approx.ftz.f32 %0, %1;" : "=f"(y) : "f"(x));
    return y;
}

// ---------------------------------------------------------------------------
// FUSED init + iter-1 row pass. Warp per row: Gumbel transform in registers
// (accurate logf inner — extremes dominate), exact row max + LSE -> R1,
// write h1 = half(s - R1) directly (fp32 s is never materialized), Rr = 0.
// DRAM-input-bound; extra registers are free here.
// ---------------------------------------------------------------------------
__global__ void __launch_bounds__(256) gs_init_row(const float* __restrict__ la,
                                                   const float* __restrict__ noise,
                                                   int b0) {
    const float EPS = 1e-20f;
    const float SC = 10.0f * LOG2E;
    int lane = threadIdx.x & 31, w = threadIdx.x >> 5;
    int rglob = b0 * N + blockIdx.x * 8 + w;
    const float4* __restrict__ arow =
        reinterpret_cast<const float4*>(la + (size_t)rglob * N);
    const float4* __restrict__ urow =
        reinterpret_cast<const float4*>(noise + (size_t)rglob * N);

    float4 sv[8];
#pragma unroll
    for (int k = 0; k < 8; k++) {
        float4 a = arow[k * 32 + lane];
        float4 u = urow[k * 32 + lane];
        sv[k].x = (a.x - __logf(EPS - logf(u.x + EPS))) * SC;
        sv[k].y = (a.y - __logf(EPS - logf(u.y + EPS))) * SC;
        sv[k].z = (a.z - __logf(EPS - logf(u.z + EPS))) * SC;
        sv[k].w = (a.w - __logf(EPS - logf(u.w + EPS))) * SC;
    }
    float m = -CUDART_INF_F;
#pragma unroll
    for (int k = 0; k < 8; k++)
        m = fmaxf(m, fmaxf(fmaxf(sv[k].x, sv[k].y), fmaxf(sv[k].z, sv[k].w)));
#pragma unroll
    for (int o = 16; o; o >>= 1) m = fmaxf(m, __shfl_xor_sync(~0u, m, o));
    float a0 = 0.f, a1 = 0.f;
#pragma unroll
    for (int k = 0; k < 8; k++) {
        a0 += ex2(sv[k].x - m) + ex2(sv[k].y - m);
        a1 += ex2(sv[k].z - m) + ex2(sv[k].w - m);
    }
    float sum = a0 + a1;
#pragma unroll
    for (int o = 16; o; o >>= 1) sum += __shfl_xor_sync(~0u, sum, o);
    float r1 = m + __log2f(sum);          // all lanes (shuffle-reduced)

    uint2* __restrict__ hrow = reinterpret_cast<uint2*>(g_h + (size_t)rglob * N);
#pragma unroll
    for (int k = 0; k < 8; k++) {
        __half2 h01 = __floats2half2_rn(sv[k].x - r1, sv[k].y - r1);
        __half2 h23 = __floats2half2_rn(sv[k].z - r1, sv[k].w - r1);
        uint2 pv;
        pv.x = *reinterpret_cast<unsigned*>(&h01);
        pv.y = *reinterpret_cast<unsigned*>(&h23);
        hrow[k * 32 + lane] = pv;
    }
    if (lane == 0) g_Rr[rglob] = 0.0f;    // Rr^1 = 0 (R1 baked into h1)
}

// ---------------------------------------------------------------------------
// fp16 row pass: Rr = log2 sum_j 2^(h1 - Cr_j)  (absolute update).
// ---------------------------------------------------------------------------
__global__ void __launch_bounds__(256) gs_row_h(int b0) {
    __shared__ float sc[N];
    int tid = threadIdx.x, lane = tid & 31, w = tid >> 5;
    int b = b0 + (blockIdx.x >> 7);
    int row = ((blockIdx.x & 127) << 3) + w;
    reinterpret_cast<float4*>(sc)[tid] =
        reinterpret_cast<const float4*>(g_Cr + (size_t)b * N)[tid];
    __syncthreads();

    const uint4* __restrict__ hrow =
        reinterpret_cast<const uint4*>(g_h + ((size_t)b * N + row) * N);
    uint4 hv[4];
#pragma unroll
    for (int k = 0; k < 4; k++) hv[k] = hrow[k * 32 + lane];

    const float4* scv = reinterpret_cast<const float4*>(sc);
    float a0 = 0.f, a1 = 0.f;
#pragma unroll
    for (int k = 0; k < 4; k++) {
        int i = k * 32 + lane;
        float4 c0 = scv[2 * i], c1 = scv[2 * i + 1];
        float2 f0 = __half22float2(*reinterpret_cast<__half2*>(&hv[k].x));
        float2 f1 = __half22float2(*reinterpret_cast<__half2*>(&hv[k].y));
        float2 f2 = __half22float2(*reinterpret_cast<__half2*>(&hv[k].z));
        float2 f3 = __half22float2(*reinterpret_cast<__half2*>(&hv[k].w));
        a0 += ex2(f0.x - c0.x) + ex2(f0.y - c0.y);
        a1 += ex2(f1.x - c0.z) + ex2(f1.y - c0.w);
        a0 += ex2(f2.x - c1.x) + ex2(f2.y - c1.y);
        a1 += ex2(f3.x - c1.z) + ex2(f3.y - c1.w);
    }
    float sum = a0 + a1;
#pragma unroll
    for (int o = 16; o; o >>= 1) sum += __shfl_xor_sync(~0u, sum, o);
    if (lane == 0) g_Rr[(size_t)b * N + row] = __log2f(sum);
}

// ---------------------------------------------------------------------------
// fp16 col pass: Cr = log2 sum_i 2^(h1 - Rr_i)  (absolute update).
// Grid (16 jc, GROUP b) = 512 blocks x 512 thr.
// ---------------------------------------------------------------------------
__global__ void __launch_bounds__(512) gs_col_h(int b0) {
    __shared__ float sr[N];
    __shared__ float part[16][66];
    int tid = threadIdx.x, lane = tid & 31, w = tid >> 5;
    int b = b0 + blockIdx.y;
    int j0 = blockIdx.x * 64;
    if (tid < 256)
        reinterpret_cast<float4*>(sr)[tid] =
            reinterpret_cast<const float4*>(g_Rr + (size_t)b * N)[tid];
    __syncthreads();

    const __half2* __restrict__ hp =
        reinterpret_cast<const __half2*>(g_h + (size_t)b * N * N + j0) + lane;
    int i0 = w * 64;
    float ax = 0.f, ay = 0.f;
#pragma unroll
    for (int ii = 0; ii < 64; ii += 8) {
        __half2 v[8];
#pragma unroll
        for (int q = 0; q < 8; q++) v[q] = hp[(size_t)(i0 + ii + q) * (N / 2)];
#pragma unroll
        for (int q = 0; q < 8; q++) {
            float rr = sr[i0 + ii + q];
            float2 f = __half22float2(v[q]);
            ax += ex2(f.x - rr);
            ay += ex2(f.y - rr);
        }
    }
    part[w][2 * lane] = ax;
    part[w][2 * lane + 1] = ay;
    __syncthreads();
    if (tid < 64) {
        float t = 0.f;
#pragma unroll
        for (int k = 0; k < 16; k++) t += part[k][tid];
        g_Cr[(size_t)b * N + j0 + tid] = __log2f(t);
    }
}

// ---------------------------------------------------------------------------
// Final: out = 2^(h1 - Rr - Cr).
// ---------------------------------------------------------------------------
__global__ void __launch_bounds__(256) gs_final(float* __restrict__ out, int b0) {
    size_t t8 = (size_t)blockIdx.x * 256 + threadIdx.x;
    size_t e = (size_t)b0 * N * N + t8 * 8;
    int row = (int)(e >> 10);
    int b = row >> 10;
    int j = (int)(e & (N - 1));
    float r = g_Rr[row];
    float4 c0 = *reinterpret_cast<const float4*>(g_Cr + (size_t)b * N + j);
    float4 c1 = *reinterpret_cast<const float4*>(g_Cr + (size_t)b * N + j + 4);
    uint4 hv = __ldcs(reinterpret_cast<const uint4*>(g_h + e));
    float2 f0 = __half22float2(*reinterpret_cast<__half2*>(&hv.x));
    float2 f1 = __half22float2(*reinterpret_cast<__half2*>(&hv.y));
    float2 f2 = __half22float2(*reinterpret_cast<__half2*>(&hv.z));
    float2 f3 = __half22float2(*reinterpret_cast<__half2*>(&hv.w));
    float4 o0, o1;
    o0.x = ex2(f0.x - r - c0.x); o0.y = ex2(f0.y - r - c0.y);
    o0.z = ex2(f1.x - r - c0.z); o0.w = ex2(f1.y - r - c0.w);
    o1.x = ex2(f2.x - r - c1.x); o1.y = ex2(f2.y - r - c1.y);
    o1.z = ex2(f3.x - r - c1.z); o1.w = ex2(f3.y - r - c1.w);
    *reinterpret_cast<float4*>(out + e) = o0;
    *reinterpret_cast<float4*>(out + e + 4) = o1;
}

// ---------------------------------------------------------------------------
// 4 groups of 32 batches; fp16 h1 (64 MB/group) is the ONLY matrix ever
// stored — fp32 s is never materialized. 41 launches per group.
// ---------------------------------------------------------------------------
extern "C" void kernel_launch(void* const* d_in, const int* in_sizes, int n_in,
                              void* d_out, int out_size) {
    const float* la = (const float*)d_in[0];
    const float* noise = (const float*)d_in[1];
    float* out = (float*)d_out;

    for (int g = 0; g < NGROUPS; g++) {
        int b0 = g * GROUP;
        gs_init_row<<<(GROUP * N) / 8, 256>>>(la, noise, b0);  // row norm 1 + pack
        gs_col_h<<<dim3(N / 64, GROUP), 512>>>(b0);            // col norm 1 (Rr=0)
        for (int t = 2; t <= NITERS; t++) {
            gs_row_h<<<(GROUP * N) / 8, 256>>>(b0);
            gs_col_h<<<dim3(N / 64, GROUP), 512>>>(b0);
        }
        gs_final<<<(GROUP * N * N) / (256 * 8), 256>>>(out, b0);
    }
}